// round 5
// baseline (speedup 1.0000x reference)
#include <cuda_runtime.h>
#include <math.h>

#define GAMMA 0.99f
#define TAUF  0.95f

constexpr int THREADS = 256;
constexpr int ITEMS   = 8;
constexpr int CHUNK   = THREADS * ITEMS;   // 2048
constexpr int NWARPS  = THREADS / 32;      // 8
constexpr int GBLK    = 512;               // persistent grid; 4/SM residency guaranteed

// Scratch (device globals; no allocation allowed)
__device__ float4 g_seg[GBLK];             // per-segment affine summary
__device__ float4 g_mA[GBLK];              // (SP, SG, SPP, SPG)
__device__ float  g_mB[GBLK];              // SGG
__device__ unsigned int g_count   = 0;
__device__ unsigned int g_release = 0;

__device__ __forceinline__ float4 ident4() { return make_float4(1.f, 0.f, 1.f, 0.f); }

// lo covers lower (earlier) indices; carry flows high->low: result = f_lo(f_hi(c))
__device__ __forceinline__ float4 comp4(float4 lo, float4 hi) {
    float4 o;
    o.x = lo.x * hi.x;
    o.y = lo.y + lo.x * hi.y;
    o.z = lo.z * hi.z;
    o.w = lo.w + lo.z * hi.w;
    return o;
}

__device__ __forceinline__ float4 shfl_down4(float4 v, int d) {
    float4 o;
    o.x = __shfl_down_sync(0xffffffffu, v.x, d);
    o.y = __shfl_down_sync(0xffffffffu, v.y, d);
    o.z = __shfl_down_sync(0xffffffffu, v.z, d);
    o.w = __shfl_down_sync(0xffffffffu, v.w, d);
    return o;
}

// Inclusive SUFFIX scan within a warp; ALL 32 lanes execute.
__device__ __forceinline__ float4 warp_suffix_scan(float4 v, int lane) {
#pragma unroll
    for (int d = 1; d < 32; d <<= 1) {
        float4 o = shfl_down4(v, d);
        if (lane + d < 32) v = comp4(v, o);
    }
    return v;
}

// Suffix scan over the first n lanes' values (whole warp participates).
__device__ __forceinline__ float4 crosswarp_suffix_scan(float4 v, int lane, int n) {
#pragma unroll
    for (int d = 1; d < 32; d <<= 1) {
        if (d >= n) break;
        float4 o = shfl_down4(v, d);
        if (lane + d < n) v = comp4(v, o);
    }
    return v;
}

// Grid-wide barrier (generation counter; safe across graph replays).
__device__ __forceinline__ void grid_barrier(unsigned int G) {
    __syncthreads();
    if (threadIdx.x == 0) {
        __threadfence();
        unsigned int gen = g_release;          // read BEFORE arriving
        unsigned int v = atomicAdd(&g_count, 1);
        if (v == G - 1) {
            g_count = 0;
            __threadfence();
            atomicAdd(&g_release, 1);
        } else {
            while (atomicAdd(&g_release, 0) == gen) { __nanosleep(64); }
        }
        __threadfence();
    }
    __syncthreads();
}

struct Tile {
    float rr[ITEMS];   // r
    float dd[ITEMS];   // delta
    float a1[ITEMS];   // gamma * mask
    int   nvalid;
};

__device__ __forceinline__ void load_tile(const float* __restrict__ r,
                                          const float* __restrict__ v,
                                          const int*   __restrict__ m,
                                          long s, long B, Tile& td) {
    float vv[ITEMS + 1];
    long rem = B - s;
    td.nvalid = (rem >= ITEMS) ? ITEMS : (rem > 0 ? (int)rem : 0);
    if (td.nvalid == ITEMS) {
#pragma unroll
        for (int j = 0; j < ITEMS / 4; j++) {
            float4 x = *reinterpret_cast<const float4*>(r + s + 4 * j);
            float4 y = *reinterpret_cast<const float4*>(v + s + 4 * j);
            int4  mi = *reinterpret_cast<const int4*>(m + s + 4 * j);
            td.rr[4*j+0] = x.x; td.rr[4*j+1] = x.y; td.rr[4*j+2] = x.z; td.rr[4*j+3] = x.w;
            vv[4*j+0] = y.x; vv[4*j+1] = y.y; vv[4*j+2] = y.z; vv[4*j+3] = y.w;
            td.a1[4*j+0] = GAMMA * (float)mi.x; td.a1[4*j+1] = GAMMA * (float)mi.y;
            td.a1[4*j+2] = GAMMA * (float)mi.z; td.a1[4*j+3] = GAMMA * (float)mi.w;
        }
        vv[ITEMS] = (s + ITEMS < B) ? v[s + ITEMS] : 0.f;
    } else {
#pragma unroll
        for (int i = 0; i < ITEMS; i++) {
            if (i < td.nvalid) {
                td.rr[i] = r[s + i];
                vv[i]    = v[s + i];
                td.a1[i] = GAMMA * (float)m[s + i];
            } else { td.rr[i] = 0.f; vv[i] = 0.f; td.a1[i] = 0.f; }
        }
        vv[ITEMS] = 0.f;
    }
#pragma unroll
    for (int i = 0; i < ITEMS; i++)
        td.dd[i] = td.rr[i] + td.a1[i] * vv[i + 1] - vv[i];
}

__device__ __forceinline__ float4 tile_summary(const Tile& td) {
    float av = 1.f, bv = 0.f, aa = 1.f, ba = 0.f;
#pragma unroll
    for (int i = 0; i < ITEMS; i++) {
        if (i < td.nvalid) {
            float a1 = td.a1[i];
            float a2 = a1 * TAUF;
            bv = bv + av * td.rr[i]; av = av * a1;
            ba = ba + aa * td.dd[i]; aa = aa * a2;
        }
    }
    return make_float4(av, bv, aa, ba);
}

__global__ void __launch_bounds__(THREADS, 4) k_fused(const float* __restrict__ r,
                                                      const float* __restrict__ v,
                                                      const int* __restrict__ m,
                                                      float* __restrict__ outA,
                                                      float* __restrict__ outVT, long B) {
    __shared__ float4 WAGG[NWARPS];
    __shared__ float2 WC[NWARPS];
    __shared__ float4 SEG;       // running segment summary (phase A)
    __shared__ float2 PG;        // (p, g): chunk carry affine in segment carry
    __shared__ float2 CAR;       // actual carry values (phase C)
    __shared__ float2 NC;        // (mean, inv_std)
    __shared__ float2 SEGCAR;    // this block's segment incoming carry
    __shared__ float SS0[NWARPS], SS1[NWARPS], SS2[NWARPS], SS3[NWARPS], SS4[NWARPS];
    __shared__ double DS[NWARPS], DQ[NWARPS];

    int t = threadIdx.x, lane = t & 31, w = t >> 5;
    int bid = blockIdx.x;
    unsigned int G = gridDim.x;

    long chunks_total = (B + CHUNK - 1) / CHUNK;
    long cpb = (chunks_total + (long)G - 1) / (long)G;
    long c_begin = (long)bid * cpb;
    long c_end = c_begin + cpb;
    if (c_end > chunks_total) c_end = chunks_total;
    if (c_begin > chunks_total) c_begin = chunks_total;

    // ---------------- Phase A: segment summary + moments ----------------
    if (t == 0) { SEG = ident4(); PG = make_float2(0.f, 1.f); }
    __syncthreads();

    float sp = 0.f, sg = 0.f, spp = 0.f, spg = 0.f, sgg = 0.f;

    for (long c = c_end - 1; c >= c_begin; c--) {
        long s = c * CHUNK + (long)t * ITEMS;
        Tile td;
        load_tile(r, v, m, s, B, td);
        float4 f = tile_summary(td);
        float4 sfx = warp_suffix_scan(f, lane);
        if (lane == 0) WAGG[w] = sfx;
        float2 pg = PG;                    // read old value before sync(1)
        __syncthreads();                   // (1) WAGG visible
        if (w == 0) {
            float4 sw = (lane < NWARPS) ? WAGG[lane] : ident4();
            sw = crosswarp_suffix_scan(sw, lane, NWARPS);
            if (lane == 0) {
                SEG = comp4(sw, SEG);
                PG = make_float2(sw.w + sw.z * pg.x, sw.z * pg.y);
            }
            float4 ex = shfl_down4(sw, 1);
            if (lane >= NWARPS - 1) ex = ident4();
            if (lane < NWARPS) WC[lane] = make_float2(ex.w, ex.z);
        }
        __syncthreads();                   // (2) WC + SEG/PG writes done
        float2 wc = WC[w];
        float4 X = shfl_down4(sfx, 1);
        if (lane == 31) X = ident4();
        float Pt = X.w + X.z * wc.x;       // thread carry vs chunk carry
        float Gt = X.z * wc.y;
        float P = Pt + Gt * pg.x;          // vs segment carry
        float Gc = Gt * pg.y;
#pragma unroll
        for (int i = ITEMS - 1; i >= 0; i--) {
            if (i < td.nvalid) {
                float a2 = td.a1[i] * TAUF;
                P  = td.dd[i] + a2 * P;
                Gc = a2 * Gc;
                sp += P; sg += Gc;
                spp += P * P; spg += P * Gc; sgg += Gc * Gc;
            }
        }
    }
    // reduce 5 moment sums block-wide
#pragma unroll
    for (int d = 16; d > 0; d >>= 1) {
        sp  += __shfl_down_sync(0xffffffffu, sp, d);
        sg  += __shfl_down_sync(0xffffffffu, sg, d);
        spp += __shfl_down_sync(0xffffffffu, spp, d);
        spg += __shfl_down_sync(0xffffffffu, spg, d);
        sgg += __shfl_down_sync(0xffffffffu, sgg, d);
    }
    if (lane == 0) { SS0[w] = sp; SS1[w] = sg; SS2[w] = spp; SS3[w] = spg; SS4[w] = sgg; }
    __syncthreads();
    if (w == 0) {
        bool ok = lane < NWARPS;
        float a0 = ok ? SS0[lane] : 0.f;
        float a1 = ok ? SS1[lane] : 0.f;
        float a2 = ok ? SS2[lane] : 0.f;
        float a3 = ok ? SS3[lane] : 0.f;
        float a4 = ok ? SS4[lane] : 0.f;
#pragma unroll
        for (int d = NWARPS / 2; d > 0; d >>= 1) {
            a0 += __shfl_down_sync(0xffffffffu, a0, d);
            a1 += __shfl_down_sync(0xffffffffu, a1, d);
            a2 += __shfl_down_sync(0xffffffffu, a2, d);
            a3 += __shfl_down_sync(0xffffffffu, a3, d);
            a4 += __shfl_down_sync(0xffffffffu, a4, d);
        }
        if (lane == 0) {
            g_mA[bid] = make_float4(a0, a1, a2, a3);
            g_mB[bid] = a4;
            g_seg[bid] = SEG;
        }
    }

    grid_barrier(G);

    // ---------------- Phase B: redundant suffix scan of segment summaries + stats ----------------
    {
        int s0 = 2 * t, s1 = 2 * t + 1;
        float4 f0 = (s0 < (int)G) ? g_seg[s0] : ident4();
        float4 f1 = (s1 < (int)G) ? g_seg[s1] : ident4();
        float4 e = comp4(f0, f1);
        float4 sfx = warp_suffix_scan(e, lane);
        if (lane == 0) WAGG[w] = sfx;
        __syncthreads();
        if (w == 0) {
            float4 sw = (lane < NWARPS) ? WAGG[lane] : ident4();
            sw = crosswarp_suffix_scan(sw, lane, NWARPS);
            float4 ex = shfl_down4(sw, 1);
            if (lane >= NWARPS - 1) ex = ident4();
            if (lane < NWARPS) WC[lane] = make_float2(ex.y, ex.w);  // VALUE carries (c=0)
        }
        __syncthreads();
        float2 wcar = WC[w];
        float4 X = shfl_down4(sfx, 1);
        if (lane == 31) X = ident4();
        float2 cpair;                       // carry entering segment s1
        cpair.x = X.y + X.x * wcar.x;
        cpair.y = X.w + X.z * wcar.y;
        float2 c0;                          // carry entering segment s0
        c0.x = f1.y + f1.x * cpair.x;
        c0.y = f1.w + f1.z * cpair.y;
        double dsum = 0.0, dssq = 0.0;
        if (s0 < (int)G) {
            float4 sA = g_mA[s0]; float sB = g_mB[s0]; float cA = c0.y;
            dsum += (double)(sA.x + sA.y * cA);
            dssq += (double)(sA.z + 2.f * sA.w * cA + sB * cA * cA);
        }
        if (s1 < (int)G) {
            float4 sA = g_mA[s1]; float sB = g_mB[s1]; float cA = cpair.y;
            dsum += (double)(sA.x + sA.y * cA);
            dssq += (double)(sA.z + 2.f * sA.w * cA + sB * cA * cA);
        }
        if (s0 == bid) SEGCAR = c0;
        if (s1 == bid) SEGCAR = cpair;
#pragma unroll
        for (int d = 16; d > 0; d >>= 1) {
            dsum += __shfl_down_sync(0xffffffffu, dsum, d);
            dssq += __shfl_down_sync(0xffffffffu, dssq, d);
        }
        if (lane == 0) { DS[w] = dsum; DQ[w] = dssq; }
        __syncthreads();
        if (w == 0) {
            bool ok = lane < NWARPS;
            double sd = ok ? DS[lane] : 0.0;
            double qd = ok ? DQ[lane] : 0.0;
#pragma unroll
            for (int d = NWARPS / 2; d > 0; d >>= 1) {
                sd += __shfl_down_sync(0xffffffffu, sd, d);
                qd += __shfl_down_sync(0xffffffffu, qd, d);
            }
            if (lane == 0) {
                double mean = sd / (double)B;
                double var  = (qd - sd * mean) / (double)(B - 1);
                NC = make_float2((float)mean, (float)(1.0 / sqrt(var)));
            }
        }
        __syncthreads();
    }

    // ---------------- Phase C: fixup + write v_target and NORMALIZED A ----------------
    float2 nc = NC;
    float mean = nc.x, istd = nc.y;
    if (t == 0) CAR = SEGCAR;
    __syncthreads();

    for (long c = c_end - 1; c >= c_begin; c--) {
        long s = c * CHUNK + (long)t * ITEMS;
        Tile td;
        load_tile(r, v, m, s, B, td);
        float4 f = tile_summary(td);
        float4 sfx = warp_suffix_scan(f, lane);
        if (lane == 0) WAGG[w] = sfx;
        float2 cb = CAR;                   // read old carry before sync(1)
        __syncthreads();                   // (1)
        if (w == 0) {
            float4 sw = (lane < NWARPS) ? WAGG[lane] : ident4();
            sw = crosswarp_suffix_scan(sw, lane, NWARPS);
            if (lane == 0)
                CAR = make_float2(sw.y + sw.x * cb.x, sw.w + sw.z * cb.y);
            float4 ex = shfl_down4(sw, 1);
            if (lane >= NWARPS - 1) ex = ident4();
            float2 wcv;
            wcv.x = ex.y + ex.x * cb.x;
            wcv.y = ex.w + ex.z * cb.y;
            if (lane < NWARPS) WC[lane] = wcv;
        }
        __syncthreads();                   // (2)
        float2 wcar = WC[w];
        float4 X = shfl_down4(sfx, 1);
        if (lane == 31) X = ident4();
        float cvt = X.y + X.x * wcar.x;
        float ca  = X.w + X.z * wcar.y;
#pragma unroll
        for (int i = ITEMS - 1; i >= 0; i--) {
            if (i < td.nvalid) {
                float a1 = td.a1[i];
                float vt = td.rr[i] + a1 * cvt;
                float A  = td.dd[i] + a1 * TAUF * ca;
                td.rr[i] = vt;
                cvt = vt; ca = A;
                td.dd[i] = (A - mean) * istd;
            }
        }
        if (td.nvalid == ITEMS) {
#pragma unroll
            for (int j2 = 0; j2 < ITEMS / 4; j2++) {
                *reinterpret_cast<float4*>(outA + s + 4 * j2) =
                    make_float4(td.dd[4*j2+0], td.dd[4*j2+1], td.dd[4*j2+2], td.dd[4*j2+3]);
                *reinterpret_cast<float4*>(outVT + s + 4 * j2) =
                    make_float4(td.rr[4*j2+0], td.rr[4*j2+1], td.rr[4*j2+2], td.rr[4*j2+3]);
            }
        } else {
            for (int i = 0; i < td.nvalid; i++) {
                outA[s + i]  = td.dd[i];
                outVT[s + i] = td.rr[i];
            }
        }
    }
}

extern "C" void kernel_launch(void* const* d_in, const int* in_sizes, int n_in,
                              void* d_out, int out_size) {
    const float* r = (const float*)d_in[0];
    const float* v = (const float*)d_in[1];
    const int*   m = (const int*)d_in[2];
    long B = (long)in_sizes[0];
    float* outA  = (float*)d_out;
    float* outVT = outA + B;

    k_fused<<<GBLK, THREADS>>>(r, v, m, outA, outVT, B);
}